// round 3
// baseline (speedup 1.0000x reference)
#include <cuda_runtime.h>
#include <math.h>

#define NTHREADS 512
#define NW 16           // warps per block = probes per round
#define NCLS 1000
#define NPAD 1024
#define NT 800
#define TSTEP 0.00125f
#define TOL 0.01f

__global__ __launch_bounds__(NTHREADS)
void logit_compression_kernel(const float* __restrict__ logits,
                              float* __restrict__ out) {
    __shared__ float dsm[NPAD];     // d_j = fl(l_j - m), padded with -inf
    __shared__ float red[NW];
    __shared__ float ctbuf[2][NW];
    __shared__ float bsh;

    const int tid  = threadIdx.x;
    const int lane = tid & 31;
    const int w    = tid >> 5;
    const int row  = blockIdx.x;
    const float* lrow = logits + row * NCLS;
    float* orow = out + row * NCLS;

    // ---- load row (2 elements per thread) ----
    float r0 = (tid < NCLS)       ? lrow[tid]       : -INFINITY;
    float r1 = (tid + 512 < NCLS) ? lrow[tid + 512] : -INFINITY;

    // ---- block max (exact) ----
    float mv = fmaxf(r0, r1);
#pragma unroll
    for (int o = 16; o > 0; o >>= 1) mv = fmaxf(mv, __shfl_xor_sync(0xffffffffu, mv, o));
    if (lane == 0) red[w] = mv;
    __syncthreads();
    if (tid < 32) {
        float v = (tid < NW) ? red[tid] : -INFINITY;
#pragma unroll
        for (int o = 8; o > 0; o >>= 1) v = fmaxf(v, __shfl_xor_sync(0xffffffffu, v, o));
        if (tid == 0) bsh = v;
    }
    __syncthreads();
    const float m = bsh;

    // ---- d -> smem; S1 with ACCURATE expf on exact d (reference-faithful) ----
    float d0 = __fsub_rn(r0, m);
    float d1 = __fsub_rn(r1, m);
    dsm[tid] = d0;
    dsm[tid + 512] = d1;
    float s1 = expf(d0) + expf(d1);          // expf(-inf)==0 for padding
#pragma unroll
    for (int o = 16; o > 0; o >>= 1) s1 += __shfl_xor_sync(0xffffffffu, s1, o);
    if (lane == 0) red[w] = s1;
    __syncthreads();
    if (tid < 32) {
        float v = (tid < NW) ? red[tid] : 0.0f;
#pragma unroll
        for (int o = 8; o > 0; o >>= 1) v += __shfl_xor_sync(0xffffffffu, v, o);
        if (tid == 0) bsh = v;
    }
    __syncthreads();                          // publishes S1 AND dsm to all warps
    const float S1 = bsh;

    // ---- warp-private register copy of d (lane-major: dd[k] = d[lane + 32k]).
    // Every warp uses the SAME layout + SAME summation tree -> conf_t values are
    // consistent and monotone across probes evaluated by different warps. ----
    float dd[32];
#pragma unroll
    for (int k = 0; k < 32; k++) dd[k] = dsm[lane + (k << 5)];

    // ---- original confidence, bin, target confidence ----
    const float conf = __fdiv_rn(1.0f, S1);
    int b = (conf >= (2.0f / 3.0f)) ? 2 : (conf >= (1.0f / 3.0f)) ? 1 : 0;
    const float BL  = (b == 0) ? 0.0f : (b == 1) ? (1.0f / 3.0f) : (2.0f / 3.0f);
    const float NBL = (b == 0) ? 0.8f : (b == 1) ? 0.86666666666f : 0.93333333333f;
    const float nc  = __fadd_rn(NBL,
                     __fmul_rn((float)(1.0 / 15.0),
                               __fdiv_rn(__fsub_rn(conf, BL), 0.2666666667f)));

    // ---- 16-way parallel search for first j with conf_t(j) >= nc - TOL ----
    // conf_t(j) monotone non-decreasing in j (temps decrease, terms shrink,
    // fixed summation tree preserves order).
    int lo = 0, hi = NT;        // hi == NT means "no true index found yet"
    float ct_hi = 0.0f;         // ct at index hi (valid when hi < NT)
    int par = 0;

    while (lo < hi) {
        const int range  = hi - lo;
        const int stride = (range + NW - 1) >> 4;     // ceil(range/16) >= 1
        const int probe  = lo + w * stride;
        float ctv = 0.0f;
        if (probe < hi) {                             // warp-uniform branch
            float t    = __fsub_rn(1.0f, __fmul_rn(TSTEP, (float)probe));
            float invt = __frcp_rn(t);                // == __fdiv_rn(1, t)
            // 4 split accumulators (fixed tree, identical in every warp)
            float a0 = 0.0f, a1 = 0.0f, a2 = 0.0f, a3 = 0.0f;
#pragma unroll
            for (int k = 0; k < 32; k += 4) {
                a0 += __expf(__fmul_rn(dd[k + 0], invt));
                a1 += __expf(__fmul_rn(dd[k + 1], invt));
                a2 += __expf(__fmul_rn(dd[k + 2], invt));
                a3 += __expf(__fmul_rn(dd[k + 3], invt));
            }
            float s = (a0 + a1) + (a2 + a3);
#pragma unroll
            for (int o = 16; o > 0; o >>= 1) s += __shfl_xor_sync(0xffffffffu, s, o);
            // reference rounding chain: ct = expf(mx - (logf(S) + mx))
            float mx  = __fmul_rn(m, invt);
            float lse = __fadd_rn(logf(s), mx);
            ctv = expf(__fsub_rn(mx, lse));
        }
        if (lane == 0) ctbuf[par][w] = ctv;
        __syncthreads();   // single barrier per round (double-buffered ctbuf)

        // All threads redundantly (deterministically) update the interval.
        int first = -1, lastvalid = 0;
#pragma unroll
        for (int i = 0; i < NW; i++) {
            int p = lo + i * stride;
            if (p < hi) {
                lastvalid = i;
                if (first < 0 && __fsub_rn(ctbuf[par][i], nc) >= -TOL) first = i;
            }
        }
        if (first >= 0) {
            ct_hi = ctbuf[par][first];
            hi = lo + first * stride;
            if (first > 0) lo = lo + (first - 1) * stride + 1;
        } else {
            lo = lo + lastvalid * stride + 1;
        }
        par ^= 1;
    }

    // ---- band check + output ----
    bool found = false;
    float tj = 1.0f;
    if (hi < NT) {
        float g = __fsub_rn(ct_hi, nc);        // >= -TOL by construction
        found = (fabsf(g) <= TOL);
        tj = __fsub_rn(1.0f, __fmul_rn(TSTEP, (float)hi));
    }
    if (tid < NCLS)       orow[tid]       = found ? __fdiv_rn(r0, tj) : r0;
    if (tid + 512 < NCLS) orow[tid + 512] = found ? __fdiv_rn(r1, tj) : r1;
}

extern "C" void kernel_launch(void* const* d_in, const int* in_sizes, int n_in,
                              void* d_out, int out_size) {
    const float* logits = (const float*)d_in[0];
    float* out = (float*)d_out;
    int B = in_sizes[0] / NCLS;   // 128 rows
    logit_compression_kernel<<<B, NTHREADS>>>(logits, out);
}

// round 4
// speedup vs baseline: 1.0627x; 1.0627x over previous
#include <cuda_runtime.h>
#include <math.h>

#define NTHREADS 256
#define NW 8            // warps per block = probes per round
#define NCLS 1000
#define NPAD 1024
#define NT 800
#define TSTEP 0.00125f
#define TOL 0.01f

__global__ __launch_bounds__(NTHREADS)
void logit_compression_kernel(const float* __restrict__ logits,
                              float* __restrict__ out) {
    __shared__ float dsm[NPAD];      // d_j = fl(l_j - m), padded with -inf
    __shared__ float red[NW];
    __shared__ float ctbuf[2][NW];
    __shared__ float bmax, bsum;

    const int tid  = threadIdx.x;
    const int lane = tid & 31;
    const int w    = tid >> 5;
    const int row  = blockIdx.x;
    const float* lrow = logits + row * NCLS;
    float* orow = out + row * NCLS;

    // ---- load row ----
    float r[4];
#pragma unroll
    for (int k = 0; k < 4; k++) {
        int idx = tid + k * NTHREADS;
        r[k] = (idx < NCLS) ? lrow[idx] : -INFINITY;
    }

    // ---- block max (exact) ----
    float mv = fmaxf(fmaxf(r[0], r[1]), fmaxf(r[2], r[3]));
#pragma unroll
    for (int o = 16; o > 0; o >>= 1) mv = fmaxf(mv, __shfl_xor_sync(0xffffffffu, mv, o));
    if (lane == 0) red[w] = mv;
    __syncthreads();
    if (tid < 32) {
        float v = (tid < NW) ? red[tid] : -INFINITY;
#pragma unroll
        for (int o = 4; o > 0; o >>= 1) v = fmaxf(v, __shfl_xor_sync(0xffffffffu, v, o));
        if (tid == 0) bmax = v;
    }
    __syncthreads();
    const float m = bmax;

    // ---- d -> smem; S1 with ACCURATE expf on exact d (reference-faithful) ----
    float s1 = 0.0f;
#pragma unroll
    for (int k = 0; k < 4; k++) {
        float dk = __fsub_rn(r[k], m);     // -inf for padding lanes
        dsm[tid + k * NTHREADS] = dk;
        s1 += expf(dk);                    // expf(-inf) == 0
    }
#pragma unroll
    for (int o = 16; o > 0; o >>= 1) s1 += __shfl_xor_sync(0xffffffffu, s1, o);
    if (lane == 0) red[w] = s1;            // red reuse: warp0 read red before prev barrier
    __syncthreads();
    if (tid < 32) {
        float v = (tid < NW) ? red[tid] : 0.0f;
#pragma unroll
        for (int o = 4; o > 0; o >>= 1) v += __shfl_xor_sync(0xffffffffu, v, o);
        if (tid == 0) bsum = v;
    }
    __syncthreads();                       // publishes bsum AND dsm to all warps
    const float S1 = bsum;

    // ---- original confidence, bin, target confidence (reference rounding) ----
    const float conf = __fdiv_rn(1.0f, S1);
    int b = (conf >= (2.0f / 3.0f)) ? 2 : (conf >= (1.0f / 3.0f)) ? 1 : 0;
    const float BL  = (b == 0) ? 0.0f : (b == 1) ? (1.0f / 3.0f) : (2.0f / 3.0f);
    const float NBL = (b == 0) ? 0.8f : (b == 1) ? 0.86666666666f : 0.93333333333f;
    const float nc  = __fadd_rn(NBL,
                     __fmul_rn((float)(1.0 / 15.0),
                               __fdiv_rn(__fsub_rn(conf, BL), 0.2666666667f)));

    // ---- interpolation-guided parallel search for first j with ct(j) >= nc - TOL.
    // ct(j) monotone non-decreasing in j (temps decrease, terms shrink, fixed
    // summation tree preserves order). Probe placement only guides WHERE we
    // evaluate; the accept/reject predicate is identical everywhere.
    const float4* d4 = (const float4*)dsm;
    const float thr_f = __fsub_rn(nc, TOL);        // guidance only

    int lo = 0, hi = NT;       // hi == NT means "no true index found yet"
    int p_lo = -1;             // position of last known-false probe
    bool have_lo = false;
    float ct_lo = 0.0f, ct_hi = 0.0f;
    int par = 0;
    const int offtab[NW] = {-8, -3, -1, 0, 1, 2, 5, 12};   // strictly ascending

    while (lo < hi) {
        const int range = hi - lo;
        const bool interp = (have_lo && hi < NT && range >= NW);
        int stride = 0, base = 0;
        if (interp) {
            float den = ct_hi - ct_lo;
            float jpf = (den > 1e-9f)
                ? (float)p_lo + (thr_f - ct_lo) * (float)(hi - p_lo) / den
                : 0.5f * (float)(lo + hi);
            base = (int)(jpf + 0.5f);
            if (base < lo)      base = lo;
            if (base > hi - 1)  base = hi - 1;
        } else {
            stride = (range + NW - 1) >> 3;        // ceil(range/8) >= 1
        }

        // my probe position (interp positions are strictly increasing in w:
        // clamp bounds lo+w .. hi-NW+w shift by +1 per w, offsets ascending)
        int pos; bool active;
        if (interp) {
            int x = base + offtab[w];
            int a = lo + w, bnd = hi - NW + w;
            pos = (x < a) ? a : ((x > bnd) ? bnd : x);
            active = true;
        } else {
            pos = lo + w * stride;
            active = (pos < hi);
        }

        float ctv = 0.0f;
        if (active) {                              // warp-uniform branch
            float t    = __fsub_rn(1.0f, __fmul_rn(TSTEP, (float)pos));
            float invt = __frcp_rn(t);
            float a0 = 0.0f, a1 = 0.0f, a2 = 0.0f, a3 = 0.0f;
#pragma unroll
            for (int k = 0; k < 8; k++) {
                float4 v = d4[lane + k * 32];
                a0 += __expf(__fmul_rn(v.x, invt));
                a1 += __expf(__fmul_rn(v.y, invt));
                a2 += __expf(__fmul_rn(v.z, invt));
                a3 += __expf(__fmul_rn(v.w, invt));
            }
            float s = (a0 + a1) + (a2 + a3);
#pragma unroll
            for (int o = 16; o > 0; o >>= 1) s += __shfl_xor_sync(0xffffffffu, s, o);
            float mx  = __fmul_rn(m, invt);
            float lse = __fadd_rn(logf(s), mx);
            ctv = expf(__fsub_rn(mx, lse));
        }
        if (lane == 0) ctbuf[par][w] = ctv;
        __syncthreads();   // single barrier per round (double-buffered ctbuf)

        // All threads redundantly (deterministically) update the interval.
        int first = -1, lastidx = 0;
        int posArr[NW];
#pragma unroll
        for (int i = 0; i < NW; i++) {
            int p; bool act;
            if (interp) {
                int x = base + offtab[i];
                int a = lo + i, bnd = hi - NW + i;
                p = (x < a) ? a : ((x > bnd) ? bnd : x);
                act = true;
            } else {
                p = lo + i * stride;
                act = (p < hi);
            }
            posArr[i] = p;
            if (act) {
                lastidx = i;
                if (first < 0 && __fsub_rn(ctbuf[par][i], nc) >= -TOL) first = i;
            }
        }
        if (first >= 0) {
            ct_hi = ctbuf[par][first];
            hi = posArr[first];
            if (first > 0) {
                p_lo = posArr[first - 1];
                ct_lo = ctbuf[par][first - 1];
                have_lo = true;
                lo = p_lo + 1;
            }
            // first == 0: hi shrinks (uniform: hi==lo -> done; interp: pos0 <= hi-8)
        } else {
            p_lo = posArr[lastidx];
            ct_lo = ctbuf[par][lastidx];
            have_lo = true;
            lo = p_lo + 1;
        }
        par ^= 1;
    }

    // ---- band check + output ----
    bool found = false;
    float tj = 1.0f;
    if (hi < NT) {
        float g = __fsub_rn(ct_hi, nc);            // >= -TOL by construction
        found = (fabsf(g) <= TOL);
        tj = __fsub_rn(1.0f, __fmul_rn(TSTEP, (float)hi));
    }
#pragma unroll
    for (int k = 0; k < 4; k++) {
        int idx = tid + k * NTHREADS;
        if (idx < NCLS) orow[idx] = found ? __fdiv_rn(r[k], tj) : r[k];
    }
}

extern "C" void kernel_launch(void* const* d_in, const int* in_sizes, int n_in,
                              void* d_out, int out_size) {
    const float* logits = (const float*)d_in[0];
    float* out = (float*)d_out;
    int B = in_sizes[0] / NCLS;   // 128 rows
    logit_compression_kernel<<<B, NTHREADS>>>(logits, out);
}